// round 17
// baseline (speedup 1.0000x reference)
#include <cuda_runtime.h>
#include <cuda_bf16.h>
#include <math.h>
#include <stdint.h>

#define N 8192
#define D 512
#define TM 128            // rows per CTA (one row block)
#define TNT 256           // cols per stripe/tile
#define KC 64             // K chunk
#define KTOP 5
#define NTHREADS 512
#define NSTRIPE 32        // 8192 / 256
#define NSLOT 36          // 2 row-scan slots + 32 col-scan slots (+2 pad)

// Scratch (no cudaMalloc allowed)
static __device__ __nv_bfloat16 g_xnb[(size_t)N * D];          // 8 MB normalized rows
static __device__ float g_part[(size_t)N * NSLOT * KTOP];      // 5.6 MB partial top-5
static __device__ float g_logrho[N];

// SMEM: A 128K | B bufs 2x32K (o>=1 epilogue stages C halves over this area) | merge 10K
#define SA_BYTES (128 * 1024)
#define SB_BYTES (32 * 1024)
#define SB0_OFF  SA_BYTES                        // 131072
#define SST_BYTES (128 * 130 * 4)                // 66560 staging (stride 130)
#define SMRG_OFF (SB0_OFF + SST_BYTES)           // 197632
#define SMEM_TOTAL (SMRG_OFF + 128 * 20 * 4)     // 207872

// ---- PTX helpers ------------------------------------------------------------
__device__ __forceinline__ uint32_t smem_u32(const void* p) {
    uint32_t a;
    asm("{ .reg .u64 t; cvta.to.shared.u64 t, %1; cvt.u32.u64 %0, t; }" : "=r"(a) : "l"(p));
    return a;
}
__device__ __forceinline__ void ldsm_x4(uint32_t* r, uint32_t addr) {
    asm volatile("ldmatrix.sync.aligned.m8n8.x4.shared.b16 {%0,%1,%2,%3}, [%4];"
                 : "=r"(r[0]), "=r"(r[1]), "=r"(r[2]), "=r"(r[3]) : "r"(addr));
}
__device__ __forceinline__ void mma_bf16(float* d, const uint32_t* a,
                                         uint32_t b0, uint32_t b1) {
    asm volatile(
        "mma.sync.aligned.m16n8k16.row.col.f32.bf16.bf16.f32 "
        "{%0,%1,%2,%3}, {%4,%5,%6,%7}, {%8,%9}, {%0,%1,%2,%3};"
        : "+f"(d[0]), "+f"(d[1]), "+f"(d[2]), "+f"(d[3])
        : "r"(a[0]), "r"(a[1]), "r"(a[2]), "r"(a[3]), "r"(b0), "r"(b1));
}
__device__ __forceinline__ void cp16(uint32_t dst, const void* src) {
    asm volatile("cp.async.cg.shared.global [%0], [%1], 16;" :: "r"(dst), "l"(src));
}
__device__ __forceinline__ void cp_commit() {
    asm volatile("cp.async.commit_group;" ::: "memory");
}
__device__ __forceinline__ void cp_wait1() {
    asm volatile("cp.async.wait_group 1;" ::: "memory");
}
__device__ __forceinline__ void cp_wait0() {
    asm volatile("cp.async.wait_group 0;" ::: "memory");
}
__device__ __forceinline__ void ins5(float v, float& t0, float& t1, float& t2,
                                     float& t3, float& t4) {
    if (v > t0) {
        t0 = v;
        if (t0 > t1) { float tm = t0; t0 = t1; t1 = tm;
          if (t1 > t2) { tm = t1; t1 = t2; t2 = tm;
            if (t2 > t3) { tm = t2; t2 = t3; t3 = tm;
              if (t3 > t4) { tm = t3; t3 = t4; t4 = tm; } } } }
    }
}

// ---------------------------------------------------------------------------
// Kernel 0: poison all partial slots.
// ---------------------------------------------------------------------------
__global__ void ginit(float* __restrict__ gpart) {
    gpart[(size_t)blockIdx.x * 1024 + threadIdx.x] = -2.f;   // N*36*5 = 1440*1024
}

// ---------------------------------------------------------------------------
// Kernel 1: row-normalize + cast to bf16. One block (128 threads) per row.
// ---------------------------------------------------------------------------
__global__ void knorm(const float* __restrict__ x, __nv_bfloat16* __restrict__ xnb) {
    int row = blockIdx.x;
    int t = threadIdx.x;
    float4 v = ((const float4*)(x + (size_t)row * D))[t];
    float s = v.x * v.x + v.y * v.y + v.z * v.z + v.w * v.w;
    #pragma unroll
    for (int o = 16; o; o >>= 1) s += __shfl_xor_sync(0xffffffffu, s, o);
    __shared__ float ws[4];
    if ((t & 31) == 0) ws[t >> 5] = s;
    __syncthreads();
    float inv = rsqrtf(ws[0] + ws[1] + ws[2] + ws[3]);
    __nv_bfloat162 p0 = __floats2bfloat162_rn(v.x * inv, v.y * inv);
    __nv_bfloat162 p1 = __floats2bfloat162_rn(v.z * inv, v.w * inv);
    uint2 o2;
    o2.x = *(uint32_t*)&p0;
    o2.y = *(uint32_t*)&p1;
    ((uint2*)(xnb + (size_t)row * D))[t] = o2;
}

// ---------------------------------------------------------------------------
// Prefetch one 256x64 bf16 K-chunk of stripe `st` into B buffer `buf`.
// ---------------------------------------------------------------------------
__device__ __forceinline__ void prefetch_B(uint32_t sb, const __nv_bfloat16* xnb,
                                           int st, int kb, int buf, int tid) {
    const uint32_t dstb = sb + SB0_OFF + (uint32_t)buf * SB_BYTES;
    const __nv_bfloat16* src = xnb + (size_t)st * TNT * D + kb * KC;
    #pragma unroll
    for (int it = 0; it < 4; it++) {
        int idx = tid + it * NTHREADS;       // 0..2047 16B chunks
        int n = idx >> 3, c16 = idx & 7;
        uint32_t off = (uint32_t)n * 128 + (uint32_t)c16 * 16;
        uint32_t sw = off ^ ((uint32_t)(n & 7) << 4);
        cp16(dstb + sw, src + (size_t)n * D + c16 * 8);
    }
    cp_commit();
}

// ---------------------------------------------------------------------------
// Kernel 2: circulant half-coverage bf16 GEMM + fused row/col top-5.
// Grid (64, 2). CTA (i,h): row block i resident; stripes at offsets
// o = 8h + tau (tau = 0..7; h=1 blocks with si<16 add o=16). Every unordered
// stripe/block pair covered exactly once. Mainloop = R12 (16 warps 4Mx4N,
// warp tile 32x64, double-buffered 32KB chunks). Row scan: persistent
// registers, one flush (slot h). Col scan (o>=1): stage each 128x128 half to
// SMEM (stride 130), 128 threads column-scan, write slot 2+2(o-1)+(i&1).
// ---------------------------------------------------------------------------
__global__ void __launch_bounds__(NTHREADS, 1)
gemm_topk(const __nv_bfloat16* __restrict__ xnb, float* __restrict__ gpart) {
    extern __shared__ char smem[];
    const uint32_t sb = smem_u32(smem);
    float* Cst = (float*)(smem + SB0_OFF);     // staging, stride 130
    float* mrg = (float*)(smem + SMRG_OFF);    // [128][20] final row merge
    const int tid = threadIdx.x;
    const int wid = tid >> 5, lane = tid & 31;
    const int wm = wid & 3;          // 4 M-groups of 32 rows
    const int wn = wid >> 2;         // 4 N-groups of 64 cols
    const int i = blockIdx.x;        // row block
    const int h = blockIdx.y;
    const int si = i >> 1;           // own stripe
    const int ntile = (h == 0) ? 8 : (si < 16 ? 9 : 8);

    const int q = lane >> 3;
    const int lr = lane & 7;
    const uint32_t swz = (uint32_t)lr << 4;

    uint32_t aoff[2], boff[4];
    #pragma unroll
    for (int mt = 0; mt < 2; mt++) {
        int arow = wm * 32 + mt * 16 + (q & 1) * 8 + lr;
        aoff[mt] = (uint32_t)arow * 1024 + (uint32_t)(q >> 1) * 16;
    }
    #pragma unroll
    for (int np = 0; np < 4; np++) {
        int bn = wn * 64 + np * 16 + (q & 1) * 8 + lr;
        boff[np] = (uint32_t)bn * 128 + (uint32_t)(q >> 1) * 16;
    }

    int rowl[4];
    #pragma unroll
    for (int mt = 0; mt < 2; mt++)
        #pragma unroll
        for (int half = 0; half < 2; half++)
            rowl[mt * 2 + half] = wm * 32 + mt * 16 + half * 8 + (lane >> 2);

    float tp[4][5];
    #pragma unroll
    for (int s = 0; s < 4; s++)
        #pragma unroll
        for (int k = 0; k < 5; k++) tp[s][k] = -2.f;

    // ---- load resident A panel (row block i), swizzled ----
    #pragma unroll
    for (int it = 0; it < 16; it++) {
        int idx = tid + it * NTHREADS;
        int r = idx >> 6, c16 = idx & 63;
        uint32_t off = (uint32_t)r * 1024 + (uint32_t)c16 * 16;
        uint32_t sw = off ^ ((uint32_t)(r & 7) << 4);
        *(uint4*)(smem + sw) =
            *(const uint4*)(xnb + (size_t)(i * TM + r) * D + c16 * 8);
    }

    // prologue: prefetch first tile's chunk0
    prefetch_B(sb, xnb, (si + h * 8) & (NSTRIPE - 1), 0, 0, tid);

    for (int tau = 0; tau < ntile; tau++) {
        const int o = h * 8 + tau;
        const int st = (si + o) & (NSTRIPE - 1);
        const int col0 = st * TNT;

        float acc[2][8][4];
        #pragma unroll
        for (int mt = 0; mt < 2; mt++)
            #pragma unroll
            for (int nt = 0; nt < 8; nt++)
                #pragma unroll
                for (int j = 0; j < 4; j++) acc[mt][nt][j] = 0.f;

        #pragma unroll
        for (int kb = 0; kb < D / KC; kb++) {
            if (kb < 7) {
                prefetch_B(sb, xnb, st, kb + 1, (kb + 1) & 1, tid);
                cp_wait1();
            } else {
                cp_wait0();
            }
            __syncthreads();

            const uint32_t bbase = sb + SB0_OFF + (uint32_t)(kb & 1) * SB_BYTES;

            #pragma unroll
            for (int k16 = 0; k16 < 4; k16++) {
                uint32_t a[2][4], b[4][4];
                #pragma unroll
                for (int mt = 0; mt < 2; mt++)
                    ldsm_x4(a[mt], sb + ((aoff[mt] + kb * 128 + k16 * 32) ^ swz));
                #pragma unroll
                for (int np = 0; np < 4; np++)
                    ldsm_x4(b[np], bbase + ((boff[np] + k16 * 32) ^ swz));
                #pragma unroll
                for (int mt = 0; mt < 2; mt++)
                    #pragma unroll
                    for (int nt = 0; nt < 8; nt++) {
                        const int np = nt >> 1, w = nt & 1;
                        mma_bf16(acc[mt][nt], a[mt], b[np][w], b[np][w + 2]);
                    }
            }
            __syncthreads();
        }

        // ---- row scan into persistent private top-5 ----
        #pragma unroll
        for (int mt = 0; mt < 2; mt++)
            #pragma unroll
            for (int half = 0; half < 2; half++) {
                const int s = mt * 2 + half;
                const int rg = i * TM + rowl[s];
                #pragma unroll
                for (int nt = 0; nt < 8; nt++)
                    #pragma unroll
                    for (int j = 0; j < 2; j++) {
                        float v = acc[mt][nt][half * 2 + j];
                        int cg = col0 + wn * 64 + nt * 8 + 2 * (lane & 3) + j;
                        if (cg != rg)
                            ins5(v, tp[s][0], tp[s][1], tp[s][2], tp[s][3], tp[s][4]);
                    }
            }

        // ---- col scan via symmetry (o >= 1): stage halves, scan columns ----
        if (o >= 1) {
            const int slot = 2 + (o - 1) * 2 + (i & 1);
            #pragma unroll
            for (int s = 0; s < 2; s++) {
                __syncthreads();   // prior staging use / B-buffer reads complete
                if ((wn >> 1) == s) {
                    #pragma unroll
                    for (int mt = 0; mt < 2; mt++)
                        #pragma unroll
                        for (int nt = 0; nt < 8; nt++)
                            #pragma unroll
                            for (int half = 0; half < 2; half++) {
                                int rl = wm * 32 + mt * 16 + half * 8 + (lane >> 2);
                                int cl = (wn & 1) * 64 + nt * 8 + 2 * (lane & 3);
                                *(float2*)&Cst[rl * 130 + cl] =
                                    make_float2(acc[mt][nt][half * 2],
                                                acc[mt][nt][half * 2 + 1]);
                            }
                }
                __syncthreads();
                if (tid < 128) {
                    float t0 = -2.f, t1 = -2.f, t2 = -2.f, t3 = -2.f, t4 = -2.f;
                    #pragma unroll 8
                    for (int r = 0; r < 128; r++)
                        ins5(Cst[r * 130 + tid], t0, t1, t2, t3, t4);
                    float* dst = gpart +
                        (size_t)(col0 + s * 128 + tid) * (NSLOT * KTOP) + slot * KTOP;
                    dst[0] = t0; dst[1] = t1; dst[2] = t2; dst[3] = t3; dst[4] = t4;
                }
            }
            __syncthreads();   // staging consumed before next prefetch/overwrite
        }

        // prefetch next tile's chunk0 (after epilogue so staging isn't clobbered)
        if (tau + 1 < ntile)
            prefetch_B(sb, xnb, (si + o + 1) & (NSTRIPE - 1), 0, 0, tid);
    }

    // ---- final row-list flush: shfl-merge 4 lanes/row -> 4 lists -> slot h ----
    #pragma unroll
    for (int s = 0; s < 4; s++) {
        #pragma unroll
        for (int off = 1; off <= 2; off <<= 1) {
            float c0 = tp[s][0], c1 = tp[s][1], c2 = tp[s][2],
                  c3 = tp[s][3], c4 = tp[s][4];
            float v0 = __shfl_xor_sync(0xffffffffu, c0, off);
            float v1 = __shfl_xor_sync(0xffffffffu, c1, off);
            float v2 = __shfl_xor_sync(0xffffffffu, c2, off);
            float v3 = __shfl_xor_sync(0xffffffffu, c3, off);
            float v4 = __shfl_xor_sync(0xffffffffu, c4, off);
            ins5(v0, tp[s][0], tp[s][1], tp[s][2], tp[s][3], tp[s][4]);
            ins5(v1, tp[s][0], tp[s][1], tp[s][2], tp[s][3], tp[s][4]);
            ins5(v2, tp[s][0], tp[s][1], tp[s][2], tp[s][3], tp[s][4]);
            ins5(v3, tp[s][0], tp[s][1], tp[s][2], tp[s][3], tp[s][4]);
            ins5(v4, tp[s][0], tp[s][1], tp[s][2], tp[s][3], tp[s][4]);
        }
    }
    __syncthreads();   // staging area free; reuse merge area safely
    if ((lane & 3) == 0) {
        #pragma unroll
        for (int s = 0; s < 4; s++) {
            float* L = mrg + rowl[s] * 20 + wn * 5;
            #pragma unroll
            for (int k = 0; k < 5; k++) L[k] = tp[s][k];
        }
    }
    __syncthreads();
    if (tid < 128) {
        float t0 = -2.f, t1 = -2.f, t2 = -2.f, t3 = -2.f, t4 = -2.f;
        #pragma unroll
        for (int k = 0; k < 20; k++)
            ins5(mrg[tid * 20 + k], t0, t1, t2, t3, t4);
        float* dst = gpart + (size_t)(i * TM + tid) * (NSLOT * KTOP) + h * KTOP;
        dst[0] = t0; dst[1] = t1; dst[2] = t2; dst[3] = t3; dst[4] = t4;
    }
}

// ---------------------------------------------------------------------------
// Kernel 3: merge 36 slot lists per row (180 floats) -> log(mean_rho + eps).
// ---------------------------------------------------------------------------
__global__ void kfinal(const float* __restrict__ gpart, float* __restrict__ lr) {
    int row = blockIdx.x * 256 + threadIdx.x;
    const float4* p = (const float4*)(gpart + (size_t)row * NSLOT * KTOP);
    float t0 = -2.f, t1 = -2.f, t2 = -2.f, t3 = -2.f, t4 = -2.f;
    #pragma unroll 9
    for (int k = 0; k < NSLOT * KTOP / 4; k++) {
        float4 v = p[k];
        ins5(v.x, t0, t1, t2, t3, t4);
        ins5(v.y, t0, t1, t2, t3, t4);
        ins5(v.z, t0, t1, t2, t3, t4);
        ins5(v.w, t0, t1, t2, t3, t4);
    }
    float sum = sqrtf(fmaxf(2.f - 2.f * t0, 0.f))
              + sqrtf(fmaxf(2.f - 2.f * t1, 0.f))
              + sqrtf(fmaxf(2.f - 2.f * t2, 0.f))
              + sqrtf(fmaxf(2.f - 2.f * t3, 0.f))
              + sqrtf(fmaxf(2.f - 2.f * t4, 0.f));
    lr[row] = logf(sum * (1.f / KTOP) + 1e-8f);
}

// ---------------------------------------------------------------------------
// Kernel 4: out = -mean(logrho)
// ---------------------------------------------------------------------------
__global__ void kred(const float* __restrict__ lr, float* __restrict__ out) {
    int t = threadIdx.x;   // 1024 threads
    float s = 0.f;
    #pragma unroll
    for (int k = 0; k < 8; k++) s += lr[t + k * 1024];
    #pragma unroll
    for (int o = 16; o; o >>= 1) s += __shfl_xor_sync(0xffffffffu, s, o);
    __shared__ float ws[32];
    if ((t & 31) == 0) ws[t >> 5] = s;
    __syncthreads();
    if (t == 0) {
        float tot = 0.f;
        #pragma unroll
        for (int k = 0; k < 32; k++) tot += ws[k];
        out[0] = -tot / (float)N;
    }
}

// ---------------------------------------------------------------------------
extern "C" void kernel_launch(void* const* d_in, const int* in_sizes, int n_in,
                              void* d_out, int out_size) {
    (void)in_sizes; (void)n_in; (void)out_size;
    const float* x = (const float*)d_in[0];
    float* out = (float*)d_out;

    __nv_bfloat16* xnb; cudaGetSymbolAddress((void**)&xnb, g_xnb);
    float* gpart;       cudaGetSymbolAddress((void**)&gpart, g_part);
    float* lrho;        cudaGetSymbolAddress((void**)&lrho, g_logrho);

    cudaFuncSetAttribute(gemm_topk, cudaFuncAttributeMaxDynamicSharedMemorySize, SMEM_TOTAL);

    ginit<<<1440, 1024>>>(gpart);
    knorm<<<N, 128>>>(x, xnb);
    gemm_topk<<<dim3(64, 2), NTHREADS, SMEM_TOTAL>>>(xnb, gpart);
    kfinal<<<N / 256, 256>>>(gpart, lrho);
    kred<<<1, 1024>>>(lrho, out);
}